// round 5
// baseline (speedup 1.0000x reference)
#include <cuda_runtime.h>
#include <math.h>
#include <stdint.h>

#define NN   200000
#define EE   600000
#define HH   128
#define OUTD 256
#define BMAXG 1024
#define BM   128
#define SCAN_B 512

// tf32 GEMM tile params
#define ASTRIDE 68     // 64-col chunk + 4 pad
#define WSTRIDE 136    // 128-col + 8 pad

// ---------------- scratch (device globals; no allocation) ----------------
__device__ float g_bufA[(size_t)NN * HH];
__device__ float g_bufB[(size_t)NN * HH];
__device__ float g_agg [(size_t)NN * HH];
__device__ int   g_deg [NN];
__device__ int   g_cur [NN];
__device__ int   g_rowptr[NN + 1];
__device__ int   g_scanTmp[NN];
__device__ int   g_bsum[2048];
__device__ int   g_adj [2 * EE];
__device__ float g_invn[NN];
__device__ float g_gsum[BMAXG * HH];
__device__ int   g_cnt [BMAXG];

// ---------------- helpers ----------------
__device__ __forceinline__ void redAdd2(float* p, float x, float y) {
    asm volatile("red.global.add.v2.f32 [%0], {%1,%2};"
                 :: "l"(p), "f"(x), "f"(y) : "memory");
}
__device__ __forceinline__ float gelu_exact(float v) {
    return 0.5f * v * (1.0f + erff(v * 0.70710678118654752f));
}
__device__ __forceinline__ float4 f4add(float4 a, float4 b) {
    return make_float4(a.x + b.x, a.y + b.y, a.z + b.z, a.w + b.w);
}
__device__ __forceinline__ float tf32r(float x) {
    float y;
    asm("cvt.rna.tf32.f32 %0, %1;" : "=f"(y) : "f"(x));
    return y;
}
__device__ __forceinline__ void mma_tf32(float* c, const uint32_t* a, uint32_t b0, uint32_t b1) {
    asm volatile(
        "mma.sync.aligned.m16n8k8.row.col.f32.tf32.tf32.f32 "
        "{%0,%1,%2,%3}, {%4,%5,%6,%7}, {%8,%9}, {%0,%1,%2,%3};"
        : "+f"(c[0]), "+f"(c[1]), "+f"(c[2]), "+f"(c[3])
        : "r"(a[0]), "r"(a[1]), "r"(a[2]), "r"(a[3]), "r"(b0), "r"(b1));
}

// ---------------- fused init: zero deg, cur, cnt, gsum ----------------
__global__ void init_k(int* __restrict__ deg, int* __restrict__ cur,
                       int* __restrict__ cnt, float* __restrict__ gsum,
                       int n, int b) {
    int i = blockIdx.x * blockDim.x + threadIdx.x;
    int s = gridDim.x * blockDim.x;
    for (int f = i; f < n; f += s) { deg[f] = 0; cur[f] = 0; }
    int g = b * HH;
    for (int f = i; f < g; f += s) gsum[f] = 0.f;
    for (int f = i; f < b; f += s) cnt[f] = 0;
}

// ---------------- degree ----------------
__global__ void deg_k(const int* __restrict__ src, const int* __restrict__ dst,
                      int* __restrict__ deg, int E) {
    int e = blockIdx.x * blockDim.x + threadIdx.x;
    if (e < E) {
        atomicAdd(&deg[src[e]], 1);
        atomicAdd(&deg[dst[e]], 1);
    }
}

// ---------------- exclusive scan (3-kernel) ----------------
__global__ void scan1_k(const int* __restrict__ deg, int* __restrict__ tmp,
                        int* __restrict__ bsum, int n) {
    __shared__ int s[SCAN_B];
    int i = blockIdx.x * SCAN_B + threadIdx.x;
    int v = (i < n) ? deg[i] : 0;
    s[threadIdx.x] = v;
    __syncthreads();
    for (int o = 1; o < SCAN_B; o <<= 1) {
        int t = 0;
        if ((int)threadIdx.x >= o) t = s[threadIdx.x - o];
        __syncthreads();
        if ((int)threadIdx.x >= o) s[threadIdx.x] += t;
        __syncthreads();
    }
    if (i < n) tmp[i] = s[threadIdx.x];
    if (threadIdx.x == SCAN_B - 1) bsum[blockIdx.x] = s[SCAN_B - 1];
}
__global__ void scan2_k(int* __restrict__ bsum, int nb) {
    __shared__ int s[1024];
    int v = ((int)threadIdx.x < nb) ? bsum[threadIdx.x] : 0;
    s[threadIdx.x] = v;
    __syncthreads();
    for (int o = 1; o < 1024; o <<= 1) {
        int t = 0;
        if ((int)threadIdx.x >= o) t = s[threadIdx.x - o];
        __syncthreads();
        if ((int)threadIdx.x >= o) s[threadIdx.x] += t;
        __syncthreads();
    }
    if ((int)threadIdx.x < nb) bsum[threadIdx.x] = s[threadIdx.x];
}
// scan3: rowptr + invn + per-graph node counts (fused)
__global__ void scan3_k(const int* __restrict__ deg, const int* __restrict__ tmp,
                        const int* __restrict__ bsum, const int* __restrict__ batch,
                        int* __restrict__ rowptr, float* __restrict__ invn,
                        int* __restrict__ cnt, int n, int Edir) {
    int i = blockIdx.x * SCAN_B + threadIdx.x;
    if (i < n) {
        int boff = (blockIdx.x > 0) ? bsum[blockIdx.x - 1] : 0;
        int d = deg[i];
        rowptr[i] = tmp[i] - d + boff;
        invn[i] = rsqrtf(fmaxf((float)d, 1.0f));
        atomicAdd(&cnt[batch[i]], 1);
    }
    if (i == 0) rowptr[n] = Edir;
}

// ---------------- CSR fill ----------------
__global__ void fill_k(const int* __restrict__ src, const int* __restrict__ dst,
                       const int* __restrict__ rowptr, int* __restrict__ cur,
                       int* __restrict__ adj, int E) {
    int e = blockIdx.x * blockDim.x + threadIdx.x;
    if (e < E) {
        int s = src[e], d = dst[e];
        int p = atomicAdd(&cur[d], 1);
        adj[rowptr[d] + p] = s;
        int q = atomicAdd(&cur[s], 1);
        adj[rowptr[s] + q] = d;
    }
}

// ---------------- embedding gather ----------------
__global__ void gather_k(const int* __restrict__ x, const float* __restrict__ emb,
                         float* __restrict__ h, int n) {
    int gt = blockIdx.x * blockDim.x + threadIdx.x;
    int nd = gt >> 5, k4 = gt & 31;
    if (nd >= n) return;
    int t = x[nd];
    ((float4*)(h + (size_t)nd * HH))[k4] = ((const float4*)(emb + (size_t)t * HH))[k4];
}

// ---------------- CSR pull-aggregation ----------------
__global__ void aggregate_k(const float* __restrict__ h, const int* __restrict__ rowptr,
                            const int* __restrict__ adj, const float* __restrict__ invn,
                            float* __restrict__ agg, int n) {
    int lane = threadIdx.x & 31;
    int v = (blockIdx.x * blockDim.x + threadIdx.x) >> 5;
    if (v >= n) return;
    int beg = rowptr[v], end = rowptr[v + 1];
    float4 a0 = make_float4(0.f, 0.f, 0.f, 0.f);
    float4 a1 = a0, a2 = a0, a3 = a0;
    int i = beg;
    for (; i + 4 <= end; i += 4) {
        int u0 = __ldg(adj + i);
        int u1 = __ldg(adj + i + 1);
        int u2 = __ldg(adj + i + 2);
        int u3 = __ldg(adj + i + 3);
        float4 v0 = __ldg(((const float4*)(h + (size_t)u0 * HH)) + lane);
        float4 v1 = __ldg(((const float4*)(h + (size_t)u1 * HH)) + lane);
        float4 v2 = __ldg(((const float4*)(h + (size_t)u2 * HH)) + lane);
        float4 v3 = __ldg(((const float4*)(h + (size_t)u3 * HH)) + lane);
        a0 = f4add(a0, v0);
        a1 = f4add(a1, v1);
        a2 = f4add(a2, v2);
        a3 = f4add(a3, v3);
    }
    for (; i < end; i++) {
        int u = __ldg(adj + i);
        a0 = f4add(a0, __ldg(((const float4*)(h + (size_t)u * HH)) + lane));
    }
    float4 s = f4add(f4add(a0, a1), f4add(a2, a3));
    float sc = invn[v];
    s.x *= sc; s.y *= sc; s.z *= sc; s.w *= sc;
    ((float4*)(agg + (size_t)v * HH))[lane] = s;
}

// ---------------- combine (TF32 tensor core) ----------------
// POOL=0: hout = gelu(agg@W + b + hprev)
// POOL=1: red-add gelu(...) into gsum[batch[row]] instead of storing hout.
template <int POOL>
__global__ void combine_tc_k(const float* __restrict__ agg, const float* __restrict__ hprev,
                             const float* __restrict__ W, const float* __restrict__ bias,
                             const int* __restrict__ batch, float* __restrict__ gsum,
                             float* __restrict__ hout, int n) {
    extern __shared__ float smem[];
    float* As = smem;                       // 128 * 68
    float* Ws = smem + 128 * ASTRIDE;       // 64 * 136
    int tid  = threadIdx.x;
    int lane = tid & 31;
    int warp = tid >> 5;
    int gid  = lane >> 2;
    int tig  = lane & 3;
    int wm   = warp >> 1;
    int wn   = warp & 1;
    int m0   = blockIdx.x * BM;
    int wm0  = wm * 32;
    int wn0  = wn * 64;

    float acc[2][8][4];
#pragma unroll
    for (int t = 0; t < 2; t++)
#pragma unroll
        for (int j = 0; j < 8; j++)
#pragma unroll
            for (int c = 0; c < 4; c++) acc[t][j][c] = 0.f;

#pragma unroll
    for (int kb = 0; kb < HH; kb += 64) {
        for (int f = tid; f < 128 * 16; f += 256) {
            int m = f >> 4, c4 = f & 15;
            int gm = m0 + m;
            float4 v = make_float4(0.f, 0.f, 0.f, 0.f);
            if (gm < n) v = __ldg((const float4*)(agg + (size_t)gm * HH + kb) + c4);
            v.x = tf32r(v.x); v.y = tf32r(v.y); v.z = tf32r(v.z); v.w = tf32r(v.w);
            *(float4*)(As + m * ASTRIDE + c4 * 4) = v;
        }
        for (int f = tid; f < 64 * 32; f += 256) {
            int k = f >> 5, n4 = f & 31;
            float4 v = __ldg((const float4*)(W + (size_t)(kb + k) * HH) + n4);
            v.x = tf32r(v.x); v.y = tf32r(v.y); v.z = tf32r(v.z); v.w = tf32r(v.w);
            *(float4*)(Ws + k * WSTRIDE + n4 * 4) = v;
        }
        __syncthreads();

#pragma unroll
        for (int kk = 0; kk < 64; kk += 8) {
            uint32_t afrag[2][4];
#pragma unroll
            for (int t = 0; t < 2; t++) {
                const float* ab = As + (wm0 + 16 * t + gid) * ASTRIDE + kk + tig;
                afrag[t][0] = __float_as_uint(ab[0]);
                afrag[t][1] = __float_as_uint(ab[8 * ASTRIDE]);
                afrag[t][2] = __float_as_uint(ab[4]);
                afrag[t][3] = __float_as_uint(ab[8 * ASTRIDE + 4]);
            }
#pragma unroll
            for (int j = 0; j < 8; j++) {
                const float* bb = Ws + (kk + tig) * WSTRIDE + wn0 + 8 * j + gid;
                uint32_t b0 = __float_as_uint(bb[0]);
                uint32_t b1 = __float_as_uint(bb[4 * WSTRIDE]);
                mma_tf32(acc[0][j], afrag[0], b0, b1);
                mma_tf32(acc[1][j], afrag[1], b0, b1);
            }
        }
        __syncthreads();
    }

    // epilogue: bias + residual + exact GELU; store OR pooled red-add
    float2 bv[8];
#pragma unroll
    for (int j = 0; j < 8; j++)
        bv[j] = *(const float2*)(bias + wn0 + 8 * j + 2 * tig);

#pragma unroll
    for (int t = 0; t < 2; t++) {
#pragma unroll
        for (int half = 0; half < 2; half++) {
            int row = m0 + wm0 + 16 * t + gid + 8 * half;
            if (row >= n) continue;
            const float* hp = hprev + (size_t)row * HH;
            float* base;
            if (POOL) {
                int b = __ldg(batch + row);
                base = gsum + (size_t)b * HH;
            } else {
                base = hout + (size_t)row * HH;
            }
#pragma unroll
            for (int j = 0; j < 8; j++) {
                int col = wn0 + 8 * j + 2 * tig;
                float2 hr = __ldg((const float2*)(hp + col));
                float ox = gelu_exact(acc[t][j][2 * half]     + bv[j].x + hr.x);
                float oy = gelu_exact(acc[t][j][2 * half + 1] + bv[j].y + hr.y);
                if (POOL) {
                    redAdd2(base + col, ox, oy);
                } else {
                    *(float2*)(base + col) = make_float2(ox, oy);
                }
            }
        }
    }
}

// ---------------- final head ----------------
__global__ void final_k(const float* __restrict__ gsum, const int* __restrict__ cnt,
                        const float* __restrict__ Wo, const float* __restrict__ bo,
                        const float* __restrict__ gamma, const float* __restrict__ beta,
                        float* __restrict__ out) {
    __shared__ float g[HH];
    __shared__ float rs[8], rq[8];
    int b = blockIdx.x, tid = threadIdx.x;
    if (tid < HH) g[tid] = gsum[(size_t)b * HH + tid] / fmaxf((float)cnt[b], 1.0f);
    __syncthreads();
    float acc = bo[tid];
#pragma unroll 4
    for (int k = 0; k < HH; k++) acc = fmaf(g[k], Wo[k * OUTD + tid], acc);
    float s = acc, q = acc * acc;
#pragma unroll
    for (int o = 16; o; o >>= 1) {
        s += __shfl_xor_sync(0xFFFFFFFFu, s, o);
        q += __shfl_xor_sync(0xFFFFFFFFu, q, o);
    }
    int w = tid >> 5;
    if ((tid & 31) == 0) { rs[w] = s; rq[w] = q; }
    __syncthreads();
    float ts = 0.f, tq = 0.f;
#pragma unroll
    for (int i = 0; i < 8; i++) { ts += rs[i]; tq += rq[i]; }
    float mu  = ts * (1.0f / OUTD);
    float var = tq * (1.0f / OUTD) - mu * mu;
    out[(size_t)b * OUTD + tid] = (acc - mu) * rsqrtf(var + 1e-5f) * gamma[tid] + beta[tid];
}

// ---------------- launch ----------------
extern "C" void kernel_launch(void* const* d_in, const int* in_sizes, int n_in,
                              void* d_out, int out_size) {
    const int* x     = (const int*)d_in[0];
    const int* ei    = (const int*)d_in[1];
    const int* batch = (const int*)d_in[2];
    int off = (n_in >= 13 && in_sizes[3] == 1) ? 4 : 3;
    const float* emb   = (const float*)d_in[off + 0];
    const float* W0    = (const float*)d_in[off + 1];
    const float* b0    = (const float*)d_in[off + 2];
    const float* W1    = (const float*)d_in[off + 3];
    const float* b1    = (const float*)d_in[off + 4];
    const float* Wo    = (const float*)d_in[off + 5];
    const float* bo    = (const float*)d_in[off + 6];
    const float* gamma = (const float*)d_in[off + 7];
    const float* beta  = (const float*)d_in[off + 8];

    int N = in_sizes[0];
    int E = in_sizes[1] / 2;
    int B = out_size / OUTD;

    float *bufA, *bufB, *agg, *invn, *gsum;
    int *deg, *cur, *rowptr, *scanTmp, *bsum, *adj, *cnt;
    cudaGetSymbolAddress((void**)&bufA, g_bufA);
    cudaGetSymbolAddress((void**)&bufB, g_bufB);
    cudaGetSymbolAddress((void**)&agg,  g_agg);
    cudaGetSymbolAddress((void**)&invn, g_invn);
    cudaGetSymbolAddress((void**)&gsum, g_gsum);
    cudaGetSymbolAddress((void**)&deg,  g_deg);
    cudaGetSymbolAddress((void**)&cur,  g_cur);
    cudaGetSymbolAddress((void**)&rowptr, g_rowptr);
    cudaGetSymbolAddress((void**)&scanTmp, g_scanTmp);
    cudaGetSymbolAddress((void**)&bsum, g_bsum);
    cudaGetSymbolAddress((void**)&adj,  g_adj);
    cudaGetSymbolAddress((void**)&cnt,  g_cnt);

    int smem_tc = (128 * ASTRIDE + 64 * WSTRIDE) * 4;   // 69632 bytes
    cudaFuncSetAttribute(combine_tc_k<0>, cudaFuncAttributeMaxDynamicSharedMemorySize, smem_tc);
    cudaFuncSetAttribute(combine_tc_k<1>, cudaFuncAttributeMaxDynamicSharedMemorySize, smem_tc);

    const int* src = ei;
    const int* dst = ei + E;

    int gthr = N * 32;
    int gblk = (gthr + 255) / 256;
    int cblk = (N + BM - 1) / BM;
    int nscan = (N + SCAN_B - 1) / SCAN_B;

    // init + CSR build
    init_k<<<256, 256>>>(deg, cur, cnt, gsum, N, B);
    deg_k<<<(E + 255) / 256, 256>>>(src, dst, deg, E);
    scan1_k<<<nscan, SCAN_B>>>(deg, scanTmp, bsum, N);
    scan2_k<<<1, 1024>>>(bsum, nscan);
    scan3_k<<<nscan, SCAN_B>>>(deg, scanTmp, bsum, batch, rowptr, invn, cnt, N, 2 * E);
    fill_k<<<(E + 255) / 256, 256>>>(src, dst, rowptr, cur, adj, E);

    // embedding
    gather_k<<<gblk, 256>>>(x, emb, bufA, N);

    // layer 1
    aggregate_k<<<(N * 32 + 255) / 256, 256>>>(bufA, rowptr, adj, invn, agg, N);
    combine_tc_k<0><<<cblk, 256, smem_tc>>>(agg, bufA, W0, b0, batch, gsum, bufB, N);

    // layer 2 (pool fused into epilogue)
    aggregate_k<<<(N * 32 + 255) / 256, 256>>>(bufB, rowptr, adj, invn, agg, N);
    combine_tc_k<1><<<cblk, 256, smem_tc>>>(agg, bufB, W1, b1, batch, gsum, bufA, N);

    // head
    final_k<<<B, 256>>>(gsum, cnt, Wo, bo, gamma, beta, (float*)d_out);
}